// round 2
// baseline (speedup 1.0000x reference)
#include <cuda_runtime.h>
#include <cstddef>

#define B_ 32
#define T_ 512
#define H_ 1024
#define G_ 4096
#define NB 128

__device__ float g_gx[(size_t)B_ * T_ * G_];
__device__ float g_out0[(size_t)B_ * T_ * H_];
__device__ float g_hT[2][H_ * B_];
__device__ unsigned g_bar;

typedef unsigned long long u64;
__device__ __forceinline__ u64 dup2(float a) {
    u64 r; asm("mov.b64 %0, {%1,%1};" : "=l"(r) : "f"(a)); return r;
}
__device__ __forceinline__ void fma2(u64& d, u64 a, u64 b) {
    asm("fma.rn.f32x2 %0, %1, %2, %0;" : "+l"(d) : "l"(a), "l"(b));
}
__device__ __forceinline__ float2 u2f(u64 v) {
    float2 f; asm("mov.b64 {%0,%1}, %2;" : "=f"(f.x), "=f"(f.y) : "l"(v)); return f;
}

// ---------------- GEMM: g_gx[r][g] = sum_k A[r][k]*W[g][k] + bias[g] ----------
#define BM 128
#define BN 128
#define BK 16

__global__ __launch_bounds__(256, 1) void gemm_bias(
    const float* __restrict__ A, const float* __restrict__ W,
    const float* __restrict__ bias)
{
    __shared__ __align__(16) float As[2][BK][BM + 4];
    __shared__ __align__(16) float Ws[2][BK][BN + 4];
    const int tid = threadIdx.x, tx = tid & 15, ty = tid >> 4;
    const int m0 = blockIdx.y * BM, n0 = blockIdx.x * BN, K = 1024;

    u64 acc[8][4];
#pragma unroll
    for (int i = 0; i < 8; ++i)
#pragma unroll
        for (int j = 0; j < 4; ++j) acc[i][j] = 0ull;

    float4 aR[2], bR[2];
#pragma unroll
    for (int u = 0; u < 2; ++u) {
        int id = tid + 256 * u, row = id >> 2, kk = (id & 3) << 2;
        aR[u] = *(const float4*)&A[(size_t)(m0 + row) * K + kk];
        bR[u] = *(const float4*)&W[(size_t)(n0 + row) * K + kk];
    }
#pragma unroll
    for (int u = 0; u < 2; ++u) {
        int id = tid + 256 * u, row = id >> 2, kk = (id & 3) << 2;
        As[0][kk][row] = aR[u].x; As[0][kk+1][row] = aR[u].y;
        As[0][kk+2][row] = aR[u].z; As[0][kk+3][row] = aR[u].w;
        Ws[0][kk][row] = bR[u].x; Ws[0][kk+1][row] = bR[u].y;
        Ws[0][kk+2][row] = bR[u].z; Ws[0][kk+3][row] = bR[u].w;
    }
    __syncthreads();

    int buf = 0;
    for (int kt = 0; kt < K / BK; ++kt) {
        if (kt + 1 < K / BK) {
            int k0 = (kt + 1) * BK;
#pragma unroll
            for (int u = 0; u < 2; ++u) {
                int id = tid + 256 * u, row = id >> 2, kk = (id & 3) << 2;
                aR[u] = *(const float4*)&A[(size_t)(m0 + row) * K + k0 + kk];
                bR[u] = *(const float4*)&W[(size_t)(n0 + row) * K + k0 + kk];
            }
        }
#pragma unroll 8
        for (int k = 0; k < BK; ++k) {
            float4 a0 = *(const float4*)&As[buf][k][ty * 8];
            float4 a1 = *(const float4*)&As[buf][k][ty * 8 + 4];
            ulonglong2 b0 = *(const ulonglong2*)&Ws[buf][k][tx * 8];
            ulonglong2 b1 = *(const ulonglong2*)&Ws[buf][k][tx * 8 + 4];
            float av[8] = {a0.x, a0.y, a0.z, a0.w, a1.x, a1.y, a1.z, a1.w};
#pragma unroll
            for (int i = 0; i < 8; ++i) {
                u64 ad = dup2(av[i]);
                fma2(acc[i][0], ad, b0.x); fma2(acc[i][1], ad, b0.y);
                fma2(acc[i][2], ad, b1.x); fma2(acc[i][3], ad, b1.y);
            }
        }
        if (kt + 1 < K / BK) {
            int nb = buf ^ 1;
#pragma unroll
            for (int u = 0; u < 2; ++u) {
                int id = tid + 256 * u, row = id >> 2, kk = (id & 3) << 2;
                As[nb][kk][row] = aR[u].x; As[nb][kk+1][row] = aR[u].y;
                As[nb][kk+2][row] = aR[u].z; As[nb][kk+3][row] = aR[u].w;
                Ws[nb][kk][row] = bR[u].x; Ws[nb][kk+1][row] = bR[u].y;
                Ws[nb][kk+2][row] = bR[u].z; Ws[nb][kk+3][row] = bR[u].w;
            }
            __syncthreads();
            buf = nb;
        }
    }
    const int nb0 = n0 + tx * 8;
    float bv[8];
#pragma unroll
    for (int j = 0; j < 8; ++j) bv[j] = bias[nb0 + j];
#pragma unroll
    for (int i = 0; i < 8; ++i) {
        size_t row = (size_t)(m0 + ty * 8 + i);
        float o[8];
#pragma unroll
        for (int p = 0; p < 4; ++p) {
            float2 f = u2f(acc[i][p]);
            o[2*p] = f.x + bv[2*p]; o[2*p+1] = f.y + bv[2*p+1];
        }
        *(float4*)&g_gx[row * G_ + nb0]     = make_float4(o[0], o[1], o[2], o[3]);
        *(float4*)&g_gx[row * G_ + nb0 + 4] = make_float4(o[4], o[5], o[6], o[7]);
    }
}

// ---------------- persistent LSTM recurrence ----------------------------------
__device__ __forceinline__ float sigf(float x) { return 1.0f / (1.0f + __expf(-x)); }

__device__ __forceinline__ void grid_bar(unsigned want) {
    __syncthreads();
    if (threadIdx.x == 0) {
        __threadfence();
        atomicAdd(&g_bar, 1u);
        unsigned v;
        do { asm volatile("ld.acquire.gpu.u32 %0, [%1];" : "=r"(v) : "l"(&g_bar)); }
        while (v < want);
    }
    __syncthreads();
}

__global__ __launch_bounds__(256, 1) void lstm_rec(
    const float* __restrict__ whh, const void* __restrict__ len_raw,
    float* __restrict__ outp, float* __restrict__ cdst, float* __restrict__ hdst)
{
    extern __shared__ float smem[];
    float* w_s = smem;                       // [32][1028]
    float* h_s = w_s + 32 * 1028;            // [128][32]
    float* g_s = h_s + 128 * 32;             // [32][36]
    int* len_s = (int*)(g_s + 32 * 36);      // [32]

    const int tid = threadIdx.x, j0 = blockIdx.x * 8;

    if (tid == 0) {
        const int* L = (const int*)len_raw;
        bool is64 = true;
        for (int i = 1; i < 32; i += 2) if (L[i] != 0) { is64 = false; break; }
        for (int b = 0; b < 32; ++b) len_s[b] = is64 ? L[2 * b] : L[b];
    }
#pragma unroll
    for (int i = 0; i < 32; ++i) {
        int idx = tid + 256 * i, rr = idx >> 8, kk = (idx & 255) << 2;
        int grow = (rr >> 3) * 1024 + j0 + (rr & 7);
        *(float4*)&w_s[rr * 1028 + kk] = *(const float4*)&whh[(size_t)grow * H_ + kk];
    }
    __syncthreads();

    const int r = tid & 31, bq = tid >> 5, b0 = bq << 2;
    const size_t gxcol = (size_t)(r >> 3) * 1024 + j0 + (r & 7);
    const int ju = tid & 7, bu = tid >> 3;
    float c_reg = 0.f, h_reg = 0.f;
    g_hT[0][(j0 + ju) * B_ + bu] = 0.f;

    unsigned want = NB;
    grid_bar(want);
    const float* wrow = &w_s[r * 1028];

    for (int t = 0; t < T_; ++t) {
        float gxv[4];
#pragma unroll
        for (int e = 0; e < 4; ++e)
            gxv[e] = __ldg(&g_gx[((size_t)(b0 + e) * T_ + t) * G_ + gxcol]);

        const float* hbuf = g_hT[t & 1];
        u64 a01 = 0ull, a23 = 0ull;
        float4 nxt[4];
#pragma unroll
        for (int u = 0; u < 4; ++u)
            nxt[u] = __ldcg((const float4*)&hbuf[(tid + 256 * u) << 2]);

        for (int kc = 0; kc < 8; ++kc) {
            __syncthreads();
#pragma unroll
            for (int u = 0; u < 4; ++u)
                *(float4*)&h_s[(tid + 256 * u) << 2] = nxt[u];
            __syncthreads();
            if (kc < 7) {
#pragma unroll
                for (int u = 0; u < 4; ++u)
                    nxt[u] = __ldcg((const float4*)&hbuf[(kc + 1) * 4096 + ((tid + 256 * u) << 2)]);
            }
            const float* wc = wrow + kc * 128;
#pragma unroll 8
            for (int kk = 0; kk < 128; kk += 4) {
                float4 w4 = *(const float4*)&wc[kk];
                float wv[4] = {w4.x, w4.y, w4.z, w4.w};
#pragma unroll
                for (int e = 0; e < 4; ++e) {
                    ulonglong2 hv = *(const ulonglong2*)&h_s[(kk + e) * 32 + b0];
                    u64 wd = dup2(wv[e]);
                    fma2(a01, wd, hv.x);
                    fma2(a23, wd, hv.y);
                }
            }
        }
        float2 f01 = u2f(a01), f23 = u2f(a23);
        *(float4*)&g_s[r * 36 + b0] = make_float4(
            f01.x + gxv[0], f01.y + gxv[1], f23.x + gxv[2], f23.y + gxv[3]);
        __syncthreads();

        float fg = sigf(g_s[(0 * 8 + ju) * 36 + bu]);
        float ig = sigf(g_s[(1 * 8 + ju) * 36 + bu]);
        float og = sigf(g_s[(2 * 8 + ju) * 36 + bu]);
        float cg = tanhf(g_s[(3 * 8 + ju) * 36 + bu]);
        float cn = fg * c_reg + ig * cg;
        float hn = og * tanhf(cn);
        if (t < len_s[bu]) { c_reg = cn; h_reg = hn; }
        g_hT[(t & 1) ^ 1][(j0 + ju) * B_ + bu] = h_reg;
        outp[((size_t)bu * T_ + t) * H_ + (j0 + ju)] = h_reg;

        want += NB;
        grid_bar(want);
    }
    cdst[(size_t)bu * H_ + j0 + ju] = c_reg;
    hdst[(size_t)bu * H_ + j0 + ju] = h_reg;
}

extern "C" void kernel_launch(void* const* d_in, const int* in_sizes, int n_in,
                              void* d_out, int out_size)
{
    const float* x    = (const float*)d_in[0];
    const void*  len  = d_in[1];
    const float* wih0 = (const float*)d_in[2];
    const float* whh0 = (const float*)d_in[3];
    const float* b0   = (const float*)d_in[4];
    const float* wih1 = (const float*)d_in[5];
    const float* whh1 = (const float*)d_in[6];
    const float* b1   = (const float*)d_in[7];
    float* out = (float*)d_out;

    void *bar_p = nullptr, *out0_p = nullptr;
    cudaGetSymbolAddress(&bar_p, g_bar);
    cudaGetSymbolAddress(&out0_p, g_out0);
    float* out0 = (float*)out0_p;

    const int SB = (32 * 1028 + 128 * 32 + 32 * 36 + 32) * 4;
    cudaFuncSetAttribute(lstm_rec, cudaFuncAttributeMaxDynamicSharedMemorySize, SB);

    const size_t O1 = (size_t)B_ * T_ * H_;
    float* c0dst = out + O1;
    float* c1dst = out + O1 + (size_t)B_ * H_;
    float* h0dst = out + O1 + 2 * (size_t)B_ * H_;
    float* h1dst = out + O1 + 3 * (size_t)B_ * H_;

    dim3 gg(G_ / BN, (B_ * T_) / BM);

    gemm_bias<<<gg, 256>>>(x, wih0, b0);
    cudaMemsetAsync(bar_p, 0, sizeof(unsigned), 0);
    lstm_rec<<<NB, 256, SB>>>(whh0, len, out0, c0dst, h0dst);

    gemm_bias<<<gg, 256>>>(out0, wih1, b1);
    cudaMemsetAsync(bar_p, 0, sizeof(unsigned), 0);
    lstm_rec<<<NB, 256, SB>>>(whh1, len, out, c1dst, h1dst);
}

// round 3
// speedup vs baseline: 1.4468x; 1.4468x over previous
#include <cuda_runtime.h>
#include <cstddef>

#define B_ 32
#define T_ 512
#define H_ 1024
#define G_ 4096
#define NB 128

__device__ float g_gx[(size_t)B_ * T_ * G_];
__device__ float g_out0[(size_t)B_ * T_ * H_];
__device__ float g_hT[2][H_ * B_];
__device__ unsigned g_bar;

typedef unsigned long long u64;
__device__ __forceinline__ u64 dup2(float a) {
    u64 r; asm("mov.b64 %0, {%1,%1};" : "=l"(r) : "f"(a)); return r;
}
__device__ __forceinline__ void fma2(u64& d, u64 a, u64 b) {
    asm("fma.rn.f32x2 %0, %1, %2, %0;" : "+l"(d) : "l"(a), "l"(b));
}
__device__ __forceinline__ void add2(u64& d, u64 a) {
    asm("add.rn.f32x2 %0, %0, %1;" : "+l"(d) : "l"(a));
}
__device__ __forceinline__ u64 pack2(float x, float y) {
    u64 r; asm("mov.b64 %0, {%1,%2};" : "=l"(r) : "f"(x), "f"(y)); return r;
}
__device__ __forceinline__ float2 u2f(u64 v) {
    float2 f; asm("mov.b64 {%0,%1}, %2;" : "=f"(f.x), "=f"(f.y) : "l"(v)); return f;
}

// ---------------- GEMM: g_gx[r][g] = sum_k A[r][k]*W[g][k] + bias[g] ----------
#define BM 128
#define BN 128
#define BK 16

__global__ __launch_bounds__(256, 1) void gemm_bias(
    const float* __restrict__ A, const float* __restrict__ W,
    const float* __restrict__ bias)
{
    __shared__ __align__(16) float As[2][BK][BM + 4];
    __shared__ __align__(16) float Ws[2][BK][BN + 4];
    const int tid = threadIdx.x, tx = tid & 15, ty = tid >> 4;
    const int m0 = blockIdx.y * BM, n0 = blockIdx.x * BN, K = 1024;

    u64 acc[8][4];
#pragma unroll
    for (int i = 0; i < 8; ++i)
#pragma unroll
        for (int j = 0; j < 4; ++j) acc[i][j] = 0ull;

    float4 aR[2], bR[2];
#pragma unroll
    for (int u = 0; u < 2; ++u) {
        int id = tid + 256 * u, row = id >> 2, kk = (id & 3) << 2;
        aR[u] = *(const float4*)&A[(size_t)(m0 + row) * K + kk];
        bR[u] = *(const float4*)&W[(size_t)(n0 + row) * K + kk];
    }
#pragma unroll
    for (int u = 0; u < 2; ++u) {
        int id = tid + 256 * u, row = id >> 2, kk = (id & 3) << 2;
        As[0][kk][row] = aR[u].x; As[0][kk+1][row] = aR[u].y;
        As[0][kk+2][row] = aR[u].z; As[0][kk+3][row] = aR[u].w;
        Ws[0][kk][row] = bR[u].x; Ws[0][kk+1][row] = bR[u].y;
        Ws[0][kk+2][row] = bR[u].z; Ws[0][kk+3][row] = bR[u].w;
    }
    __syncthreads();

    int buf = 0;
    for (int kt = 0; kt < K / BK; ++kt) {
        if (kt + 1 < K / BK) {
            int k0 = (kt + 1) * BK;
#pragma unroll
            for (int u = 0; u < 2; ++u) {
                int id = tid + 256 * u, row = id >> 2, kk = (id & 3) << 2;
                aR[u] = *(const float4*)&A[(size_t)(m0 + row) * K + k0 + kk];
                bR[u] = *(const float4*)&W[(size_t)(n0 + row) * K + k0 + kk];
            }
        }
#pragma unroll 8
        for (int k = 0; k < BK; ++k) {
            float4 a0 = *(const float4*)&As[buf][k][ty * 8];
            float4 a1 = *(const float4*)&As[buf][k][ty * 8 + 4];
            ulonglong2 b0 = *(const ulonglong2*)&Ws[buf][k][tx * 8];
            ulonglong2 b1 = *(const ulonglong2*)&Ws[buf][k][tx * 8 + 4];
            float av[8] = {a0.x, a0.y, a0.z, a0.w, a1.x, a1.y, a1.z, a1.w};
#pragma unroll
            for (int i = 0; i < 8; ++i) {
                u64 ad = dup2(av[i]);
                fma2(acc[i][0], ad, b0.x); fma2(acc[i][1], ad, b0.y);
                fma2(acc[i][2], ad, b1.x); fma2(acc[i][3], ad, b1.y);
            }
        }
        if (kt + 1 < K / BK) {
            int nb = buf ^ 1;
#pragma unroll
            for (int u = 0; u < 2; ++u) {
                int id = tid + 256 * u, row = id >> 2, kk = (id & 3) << 2;
                As[nb][kk][row] = aR[u].x; As[nb][kk+1][row] = aR[u].y;
                As[nb][kk+2][row] = aR[u].z; As[nb][kk+3][row] = aR[u].w;
                Ws[nb][kk][row] = bR[u].x; Ws[nb][kk+1][row] = bR[u].y;
                Ws[nb][kk+2][row] = bR[u].z; Ws[nb][kk+3][row] = bR[u].w;
            }
            __syncthreads();
            buf = nb;
        }
    }
    const int nb0 = n0 + tx * 8;
    float bv[8];
#pragma unroll
    for (int j = 0; j < 8; ++j) bv[j] = bias[nb0 + j];
#pragma unroll
    for (int i = 0; i < 8; ++i) {
        size_t row = (size_t)(m0 + ty * 8 + i);
        float o[8];
#pragma unroll
        for (int p = 0; p < 4; ++p) {
            float2 f = u2f(acc[i][p]);
            o[2*p] = f.x + bv[2*p]; o[2*p+1] = f.y + bv[2*p+1];
        }
        *(float4*)&g_gx[row * G_ + nb0]     = make_float4(o[0], o[1], o[2], o[3]);
        *(float4*)&g_gx[row * G_ + nb0 + 4] = make_float4(o[4], o[5], o[6], o[7]);
    }
}

// ---------------- persistent LSTM recurrence ----------------------------------
__device__ __forceinline__ float sigf(float x) { return 1.0f / (1.0f + __expf(-x)); }

__device__ __forceinline__ void grid_bar(unsigned want) {
    __syncthreads();
    if (threadIdx.x == 0) {
        __threadfence();
        atomicAdd(&g_bar, 1u);
        unsigned v;
        do { asm volatile("ld.acquire.gpu.u32 %0, [%1];" : "=r"(v) : "l"(&g_bar)); }
        while (v < want);
    }
    __syncthreads();
}

// SMEM: w_s[1024][32] | hb[2][128][32] | red[8][32][32] | g_s[32][36] | len[32]
#define SM_W   (1024 * 32)
#define SM_HB  (2 * 128 * 32)
#define SM_RED (8 * 32 * 32)
#define SM_GS  (32 * 36)
#define SM_TOT ((SM_W + SM_HB + SM_RED + SM_GS + 32) * 4)

__global__ __launch_bounds__(256, 1) void lstm_rec(
    const float* __restrict__ whh, const void* __restrict__ len_raw,
    float* __restrict__ outp, float* __restrict__ cdst, float* __restrict__ hdst)
{
    extern __shared__ float smem[];
    float* w_s = smem;                 // [1024][32] transposed slice of W_hh
    float* hb  = w_s + SM_W;           // [2][128][32] h double buffer
    float* red = hb + SM_HB;           // [8][32][32] cross-warp partials
    float* g_s = red + SM_RED;         // [32][36] gate exchange
    int* len_s = (int*)(g_s + SM_GS);

    const int tid = threadIdx.x, j0 = blockIdx.x * 8;

    if (tid == 0) {
        const int* L = (const int*)len_raw;
        bool is64 = true;
        for (int i = 1; i < 32; i += 2) if (L[i] != 0) { is64 = false; break; }
        for (int b = 0; b < 32; ++b) len_s[b] = is64 ? L[2 * b] : L[b];
    }

    // stage W_hh slice transposed: w_s[k*32 + r] = whh[grow(r)*H + k]
    {
        const int r = tid & 31;
        const int grow = (r >> 3) * 1024 + j0 + (r & 7);
        const int k0 = (tid >> 5) * 128;
        const float* src = &whh[(size_t)grow * H_ + k0];
#pragma unroll
        for (int kk = 0; kk < 128; kk += 4) {
            float4 v = *(const float4*)&src[kk];
            w_s[(k0 + kk + 0) * 32 + r] = v.x;
            w_s[(k0 + kk + 1) * 32 + r] = v.y;
            w_s[(k0 + kk + 2) * 32 + r] = v.z;
            w_s[(k0 + kk + 3) * 32 + r] = v.w;
        }
    }
    __syncthreads();

    // compute-phase mapping: 4 rows x 8 batch per thread, K split over warps
    const int rg = tid & 7;            // row group: rows 4*rg..4*rg+3
    const int bg = (tid >> 3) & 3;     // batch group: b 8*bg..8*bg+7
    const int ks = tid >> 5;           // warp's k-slice within each 128-chunk

    // output-stage mapping
    const int ro = tid >> 3;           // row 0..31
    const int bq = tid & 7;            // batch quad: b 4*bq..4*bq+3
    const size_t ocol = (size_t)(ro >> 3) * 1024 + j0 + (ro & 7);

    // update-stage mapping
    const int ju = tid & 7, bu = tid >> 3;
    float c_reg = 0.f, h_reg = 0.f;
    g_hT[0][(j0 + ju) * B_ + bu] = 0.f;

    unsigned want = NB;
    grid_bar(want);

    u64* redu = (u64*)red;             // [8][32][16]

    for (int t = 0; t < T_; ++t) {
        u64 acc[4][4];
#pragma unroll
        for (int i = 0; i < 4; ++i)
#pragma unroll
            for (int j = 0; j < 4; ++j) acc[i][j] = 0ull;

        const float* hbuf = g_hT[t & 1];
        float4 nxt[4];
#pragma unroll
        for (int u = 0; u < 4; ++u)
            nxt[u] = __ldcg((const float4*)&hbuf[(tid + 256 * u) << 2]);

        for (int kc = 0; kc < 8; ++kc) {
            __syncthreads();
            float* hcur = &hb[(kc & 1) * 4096];
#pragma unroll
            for (int u = 0; u < 4; ++u)
                *(float4*)&hcur[(tid + 256 * u) << 2] = nxt[u];
            __syncthreads();
            if (kc < 7) {
#pragma unroll
                for (int u = 0; u < 4; ++u)
                    nxt[u] = __ldcg((const float4*)&hbuf[(kc + 1) * 4096 + ((tid + 256 * u) << 2)]);
            }
            const float* wk = &w_s[(kc * 128 + ks * 16) * 32 + rg * 4];
            const float* hk = &hcur[(ks * 16) * 32 + bg * 8];
#pragma unroll
            for (int kk = 0; kk < 16; ++kk) {
                float4 w4 = *(const float4*)&wk[kk * 32];
                ulonglong2 hA = *(const ulonglong2*)&hk[kk * 32];
                ulonglong2 hB = *(const ulonglong2*)&hk[kk * 32 + 4];
                u64 w0 = dup2(w4.x), w1 = dup2(w4.y), w2 = dup2(w4.z), w3 = dup2(w4.w);
                fma2(acc[0][0], w0, hA.x); fma2(acc[0][1], w0, hA.y);
                fma2(acc[0][2], w0, hB.x); fma2(acc[0][3], w0, hB.y);
                fma2(acc[1][0], w1, hA.x); fma2(acc[1][1], w1, hA.y);
                fma2(acc[1][2], w1, hB.x); fma2(acc[1][3], w1, hB.y);
                fma2(acc[2][0], w2, hA.x); fma2(acc[2][1], w2, hA.y);
                fma2(acc[2][2], w2, hB.x); fma2(acc[2][3], w2, hB.y);
                fma2(acc[3][0], w3, hA.x); fma2(acc[3][1], w3, hA.y);
                fma2(acc[3][2], w3, hB.x); fma2(acc[3][3], w3, hB.y);
            }
        }

        // cross-warp reduction: redu[ks][row][bpair]
#pragma unroll
        for (int i = 0; i < 4; ++i) {
            *(ulonglong2*)&redu[((size_t)ks * 32 + rg * 4 + i) * 16 + bg * 4] =
                make_ulonglong2(acc[i][0], acc[i][1]);
            *(ulonglong2*)&redu[((size_t)ks * 32 + rg * 4 + i) * 16 + bg * 4 + 2] =
                make_ulonglong2(acc[i][2], acc[i][3]);
        }
        __syncthreads();

        // sum 8 partials, add gx, write gates to g_s
        {
            u64 o0 = redu[(size_t)ro * 16 + bq * 2];
            u64 o1 = redu[(size_t)ro * 16 + bq * 2 + 1];
#pragma unroll
            for (int s = 1; s < 8; ++s) {
                add2(o0, redu[((size_t)s * 32 + ro) * 16 + bq * 2]);
                add2(o1, redu[((size_t)s * 32 + ro) * 16 + bq * 2 + 1]);
            }
            const int b0 = bq * 4;
            float gx0 = __ldg(&g_gx[((size_t)(b0 + 0) * T_ + t) * G_ + ocol]);
            float gx1 = __ldg(&g_gx[((size_t)(b0 + 1) * T_ + t) * G_ + ocol]);
            float gx2 = __ldg(&g_gx[((size_t)(b0 + 2) * T_ + t) * G_ + ocol]);
            float gx3 = __ldg(&g_gx[((size_t)(b0 + 3) * T_ + t) * G_ + ocol]);
            add2(o0, pack2(gx0, gx1));
            add2(o1, pack2(gx2, gx3));
            float2 f0 = u2f(o0), f1 = u2f(o1);
            *(float4*)&g_s[ro * 36 + b0] = make_float4(f0.x, f0.y, f1.x, f1.y);
        }
        __syncthreads();

        // pointwise LSTM update for (j0+ju, bu)
        {
            float fg = sigf(g_s[(0 * 8 + ju) * 36 + bu]);
            float ig = sigf(g_s[(1 * 8 + ju) * 36 + bu]);
            float og = sigf(g_s[(2 * 8 + ju) * 36 + bu]);
            float cg = tanhf(g_s[(3 * 8 + ju) * 36 + bu]);
            float cn = fg * c_reg + ig * cg;
            float hn = og * tanhf(cn);
            if (t < len_s[bu]) { c_reg = cn; h_reg = hn; }
            g_hT[(t & 1) ^ 1][(j0 + ju) * B_ + bu] = h_reg;
            outp[((size_t)bu * T_ + t) * H_ + (j0 + ju)] = h_reg;
        }

        want += NB;
        grid_bar(want);
    }
    cdst[(size_t)bu * H_ + j0 + ju] = c_reg;
    hdst[(size_t)bu * H_ + j0 + ju] = h_reg;
}

extern "C" void kernel_launch(void* const* d_in, const int* in_sizes, int n_in,
                              void* d_out, int out_size)
{
    const float* x    = (const float*)d_in[0];
    const void*  len  = d_in[1];
    const float* wih0 = (const float*)d_in[2];
    const float* whh0 = (const float*)d_in[3];
    const float* b0   = (const float*)d_in[4];
    const float* wih1 = (const float*)d_in[5];
    const float* whh1 = (const float*)d_in[6];
    const float* b1   = (const float*)d_in[7];
    float* out = (float*)d_out;

    void *bar_p = nullptr, *out0_p = nullptr;
    cudaGetSymbolAddress(&bar_p, g_bar);
    cudaGetSymbolAddress(&out0_p, g_out0);
    float* out0 = (float*)out0_p;

    cudaFuncSetAttribute(lstm_rec, cudaFuncAttributeMaxDynamicSharedMemorySize, SM_TOT);

    const size_t O1 = (size_t)B_ * T_ * H_;
    float* c0dst = out + O1;
    float* c1dst = out + O1 + (size_t)B_ * H_;
    float* h0dst = out + O1 + 2 * (size_t)B_ * H_;
    float* h1dst = out + O1 + 3 * (size_t)B_ * H_;

    dim3 gg(G_ / BN, (B_ * T_) / BM);

    gemm_bias<<<gg, 256>>>(x, wih0, b0);
    cudaMemsetAsync(bar_p, 0, sizeof(unsigned), 0);
    lstm_rec<<<NB, 256, SM_TOT>>>(whh0, len, out0, c0dst, h0dst);

    gemm_bias<<<gg, 256>>>(out0, wih1, b1);
    cudaMemsetAsync(bar_p, 0, sizeof(unsigned), 0);
    lstm_rec<<<NB, 256, SM_TOT>>>(whh1, len, out, c1dst, h1dst);
}

// round 4
// speedup vs baseline: 1.8781x; 1.2981x over previous
#include <cuda_runtime.h>
#include <cuda_bf16.h>
#include <cstddef>

#define B_ 32
#define T_ 512
#define H_ 1024
#define G_ 4096
#define NB 128

__device__ float g_gx[(size_t)B_ * T_ * G_];
__device__ float g_out0[(size_t)B_ * T_ * H_];
__device__ float g_hT[2][H_ * B_];
__device__ unsigned g_bar;
__device__ __nv_bfloat16 g_Ahi[(size_t)B_ * T_ * H_];
__device__ __nv_bfloat16 g_Alo[(size_t)B_ * T_ * H_];
__device__ __nv_bfloat16 g_Whi[(size_t)G_ * H_];
__device__ __nv_bfloat16 g_Wlo[(size_t)G_ * H_];

typedef unsigned long long u64;
__device__ __forceinline__ u64 dup2(float a) {
    u64 r; asm("mov.b64 %0, {%1,%1};" : "=l"(r) : "f"(a)); return r;
}
__device__ __forceinline__ void fma2(u64& d, u64 a, u64 b) {
    asm("fma.rn.f32x2 %0, %1, %2, %0;" : "+l"(d) : "l"(a), "l"(b));
}
__device__ __forceinline__ void add2(u64& d, u64 a) {
    asm("add.rn.f32x2 %0, %0, %1;" : "+l"(d) : "l"(a));
}
__device__ __forceinline__ u64 pack2(float x, float y) {
    u64 r; asm("mov.b64 %0, {%1,%2};" : "=l"(r) : "f"(x), "f"(y)); return r;
}
__device__ __forceinline__ float2 u2f(u64 v) {
    float2 f; asm("mov.b64 {%0,%1}, %2;" : "=f"(f.x), "=f"(f.y) : "l"(v)); return f;
}

// ---------------- hi/lo bf16 split conversion ---------------------------------
__global__ __launch_bounds__(256) void conv_split(
    const float* __restrict__ s, __nv_bfloat16* __restrict__ hi,
    __nv_bfloat16* __restrict__ lo, int n4)
{
    int i = blockIdx.x * 256 + threadIdx.x;
    if (i >= n4) return;
    float4 v = ((const float4*)s)[i];
    __nv_bfloat16 h0 = __float2bfloat16(v.x), h1 = __float2bfloat16(v.y);
    __nv_bfloat16 h2 = __float2bfloat16(v.z), h3 = __float2bfloat16(v.w);
    __nv_bfloat16 l0 = __float2bfloat16(v.x - __bfloat162float(h0));
    __nv_bfloat16 l1 = __float2bfloat16(v.y - __bfloat162float(h1));
    __nv_bfloat16 l2 = __float2bfloat16(v.z - __bfloat162float(h2));
    __nv_bfloat16 l3 = __float2bfloat16(v.w - __bfloat162float(h3));
    ((__nv_bfloat162*)hi)[i * 2]     = __nv_bfloat162(h0, h1);
    ((__nv_bfloat162*)hi)[i * 2 + 1] = __nv_bfloat162(h2, h3);
    ((__nv_bfloat162*)lo)[i * 2]     = __nv_bfloat162(l0, l1);
    ((__nv_bfloat162*)lo)[i * 2 + 1] = __nv_bfloat162(l2, l3);
}

// ---------------- tensor-core GEMM: g_gx = A@W^T + bias (bf16x3 split) --------
__device__ __forceinline__ void ldsm4(unsigned* r, unsigned a) {
    asm volatile("ldmatrix.sync.aligned.m8n8.x4.shared.b16 {%0,%1,%2,%3}, [%4];"
                 : "=r"(r[0]), "=r"(r[1]), "=r"(r[2]), "=r"(r[3]) : "r"(a));
}
__device__ __forceinline__ void mma16816(float* c, const unsigned* a,
                                         unsigned b0, unsigned b1) {
    asm volatile(
        "mma.sync.aligned.m16n8k16.row.col.f32.bf16.bf16.f32 "
        "{%0,%1,%2,%3}, {%4,%5,%6,%7}, {%8,%9}, {%0,%1,%2,%3};"
        : "+f"(c[0]), "+f"(c[1]), "+f"(c[2]), "+f"(c[3])
        : "r"(a[0]), "r"(a[1]), "r"(a[2]), "r"(a[3]), "r"(b0), "r"(b1));
}
__device__ __forceinline__ void cpa(unsigned s, const void* g) {
    asm volatile("cp.async.cg.shared.global [%0], [%1], 16;" :: "r"(s), "l"(g));
}

#define SR 40                       // smem row stride (bf16 elems)
#define BUFB (128 * SR * 2)         // bytes per buffer = 10240
#define OFF_AH 0
#define OFF_AL (2 * BUFB)
#define OFF_BH (4 * BUFB)
#define OFF_BL (6 * BUFB)
#define TC_SMEM (8 * BUFB)          // 81920

__global__ __launch_bounds__(256, 1) void tc_gemm(
    const __nv_bfloat16* __restrict__ Ahi, const __nv_bfloat16* __restrict__ Alo,
    const __nv_bfloat16* __restrict__ Whi, const __nv_bfloat16* __restrict__ Wlo,
    const float* __restrict__ bias)
{
    extern __shared__ char sm[];
    const unsigned sbase = (unsigned)__cvta_generic_to_shared(sm);
    const int tid = threadIdx.x, lane = tid & 31, wid = tid >> 5;
    const int wm = wid & 3, wn = wid >> 2;
    const int m0 = blockIdx.y * 128, n0 = blockIdx.x * 128;

    // fill addressing: id -> (row, chunk-of-8)
    int frow[2], fch[2];
    unsigned sA[2], sB[2];
#pragma unroll
    for (int u = 0; u < 2; ++u) {
        int id = tid + 256 * u;
        frow[u] = id >> 2; fch[u] = (id & 3) * 8;
        sA[u] = (frow[u] * SR + fch[u]) * 2;
        sB[u] = sA[u];
    }

    // ldmatrix per-thread base offsets
    const int arow = wm * 32 + (lane & 7) + (lane & 8);
    const unsigned a_base = (arow * SR + (lane >> 4) * 8) * 2;
    const int brow = wn * 64 + (lane & 7) + (lane >> 4) * 8;
    const unsigned b_base = (brow * SR + ((lane >> 3) & 1) * 8) * 2;

    float c[2][8][4];
#pragma unroll
    for (int i = 0; i < 2; ++i)
#pragma unroll
        for (int j = 0; j < 8; ++j)
#pragma unroll
            for (int q = 0; q < 4; ++q) c[i][j][q] = 0.f;

    // prologue: stage 0
#pragma unroll
    for (int u = 0; u < 2; ++u) {
        size_t ga = (size_t)(m0 + frow[u]) * H_ + fch[u];
        size_t gb = (size_t)(n0 + frow[u]) * H_ + fch[u];
        cpa(sbase + OFF_AH + sA[u], &Ahi[ga]);
        cpa(sbase + OFF_AL + sA[u], &Alo[ga]);
        cpa(sbase + OFF_BH + sB[u], &Whi[gb]);
        cpa(sbase + OFF_BL + sB[u], &Wlo[gb]);
    }
    asm volatile("cp.async.commit_group;");

    for (int s = 0; s < 32; ++s) {
        asm volatile("cp.async.wait_group 0;");
        __syncthreads();
        if (s + 1 < 32) {
            int k0 = (s + 1) * 32, bf = (s + 1) & 1;
#pragma unroll
            for (int u = 0; u < 2; ++u) {
                size_t ga = (size_t)(m0 + frow[u]) * H_ + k0 + fch[u];
                size_t gb = (size_t)(n0 + frow[u]) * H_ + k0 + fch[u];
                cpa(sbase + OFF_AH + bf * BUFB + sA[u], &Ahi[ga]);
                cpa(sbase + OFF_AL + bf * BUFB + sA[u], &Alo[ga]);
                cpa(sbase + OFF_BH + bf * BUFB + sB[u], &Whi[gb]);
                cpa(sbase + OFF_BL + bf * BUFB + sB[u], &Wlo[gb]);
            }
            asm volatile("cp.async.commit_group;");
        }
        const unsigned bo = (s & 1) * BUFB;
#pragma unroll
        for (int kk = 0; kk < 2; ++kk) {
            unsigned ah[2][4], al[2][4], bh[4][4], bl[4][4];
#pragma unroll
            for (int mi = 0; mi < 2; ++mi) {
                unsigned ad = sbase + bo + a_base + mi * (16 * SR * 2) + kk * 32;
                ldsm4(ah[mi], ad + OFF_AH);
                ldsm4(al[mi], ad + OFF_AL);
            }
#pragma unroll
            for (int j = 0; j < 4; ++j) {
                unsigned bd = sbase + bo + b_base + j * (16 * SR * 2) + kk * 32;
                ldsm4(bh[j], bd + OFF_BH);
                ldsm4(bl[j], bd + OFF_BL);
            }
#pragma unroll
            for (int mi = 0; mi < 2; ++mi)
#pragma unroll
                for (int j = 0; j < 4; ++j) {
                    mma16816(c[mi][2*j],   ah[mi], bh[j][0], bh[j][1]);
                    mma16816(c[mi][2*j+1], ah[mi], bh[j][2], bh[j][3]);
                    mma16816(c[mi][2*j],   ah[mi], bl[j][0], bl[j][1]);
                    mma16816(c[mi][2*j+1], ah[mi], bl[j][2], bl[j][3]);
                    mma16816(c[mi][2*j],   al[mi], bh[j][0], bh[j][1]);
                    mma16816(c[mi][2*j+1], al[mi], bh[j][2], bh[j][3]);
                }
        }
        __syncthreads();
    }

    // epilogue: bias + store fp32
#pragma unroll
    for (int mi = 0; mi < 2; ++mi) {
        int gr = m0 + wm * 32 + mi * 16 + (lane >> 2);
#pragma unroll
        for (int ni = 0; ni < 8; ++ni) {
            int gc = n0 + wn * 64 + ni * 8 + (lane & 3) * 2;
            float2 bv = *(const float2*)&bias[gc];
            float* cc = c[mi][ni];
            *(float2*)&g_gx[(size_t)gr * G_ + gc] =
                make_float2(cc[0] + bv.x, cc[1] + bv.y);
            *(float2*)&g_gx[(size_t)(gr + 8) * G_ + gc] =
                make_float2(cc[2] + bv.x, cc[3] + bv.y);
        }
    }
}

// ---------------- persistent LSTM recurrence (unchanged from R3) --------------
__device__ __forceinline__ float sigf(float x) { return 1.0f / (1.0f + __expf(-x)); }

__device__ __forceinline__ void grid_bar(unsigned want) {
    __syncthreads();
    if (threadIdx.x == 0) {
        __threadfence();
        atomicAdd(&g_bar, 1u);
        unsigned v;
        do { asm volatile("ld.acquire.gpu.u32 %0, [%1];" : "=r"(v) : "l"(&g_bar)); }
        while (v < want);
    }
    __syncthreads();
}

#define SM_W   (1024 * 32)
#define SM_HB  (2 * 128 * 32)
#define SM_RED (8 * 32 * 32)
#define SM_GS  (32 * 36)
#define SM_TOT ((SM_W + SM_HB + SM_RED + SM_GS + 32) * 4)

__global__ __launch_bounds__(256, 1) void lstm_rec(
    const float* __restrict__ whh, const void* __restrict__ len_raw,
    float* __restrict__ outp, float* __restrict__ cdst, float* __restrict__ hdst)
{
    extern __shared__ float smem[];
    float* w_s = smem;
    float* hb  = w_s + SM_W;
    float* red = hb + SM_HB;
    float* g_s = red + SM_RED;
    int* len_s = (int*)(g_s + SM_GS);

    const int tid = threadIdx.x, j0 = blockIdx.x * 8;

    if (tid == 0) {
        const int* L = (const int*)len_raw;
        bool is64 = true;
        for (int i = 1; i < 32; i += 2) if (L[i] != 0) { is64 = false; break; }
        for (int b = 0; b < 32; ++b) len_s[b] = is64 ? L[2 * b] : L[b];
    }
    {
        const int r = tid & 31;
        const int grow = (r >> 3) * 1024 + j0 + (r & 7);
        const int k0 = (tid >> 5) * 128;
        const float* src = &whh[(size_t)grow * H_ + k0];
#pragma unroll
        for (int kk = 0; kk < 128; kk += 4) {
            float4 v = *(const float4*)&src[kk];
            w_s[(k0 + kk + 0) * 32 + r] = v.x;
            w_s[(k0 + kk + 1) * 32 + r] = v.y;
            w_s[(k0 + kk + 2) * 32 + r] = v.z;
            w_s[(k0 + kk + 3) * 32 + r] = v.w;
        }
    }
    __syncthreads();

    const int rg = tid & 7;
    const int bg = (tid >> 3) & 3;
    const int ks = tid >> 5;
    const int ro = tid >> 3;
    const int bq = tid & 7;
    const size_t ocol = (size_t)(ro >> 3) * 1024 + j0 + (ro & 7);
    const int ju = tid & 7, bu = tid >> 3;
    float c_reg = 0.f, h_reg = 0.f;
    g_hT[0][(j0 + ju) * B_ + bu] = 0.f;

    unsigned want = NB;
    grid_bar(want);
    u64* redu = (u64*)red;

    for (int t = 0; t < T_; ++t) {
        u64 acc[4][4];
#pragma unroll
        for (int i = 0; i < 4; ++i)
#pragma unroll
            for (int j = 0; j < 4; ++j) acc[i][j] = 0ull;

        const float* hbuf = g_hT[t & 1];
        float4 nxt[4];
#pragma unroll
        for (int u = 0; u < 4; ++u)
            nxt[u] = __ldcg((const float4*)&hbuf[(tid + 256 * u) << 2]);

        for (int kc = 0; kc < 8; ++kc) {
            __syncthreads();
            float* hcur = &hb[(kc & 1) * 4096];
#pragma unroll
            for (int u = 0; u < 4; ++u)
                *(float4*)&hcur[(tid + 256 * u) << 2] = nxt[u];
            __syncthreads();
            if (kc < 7) {
#pragma unroll
                for (int u = 0; u < 4; ++u)
                    nxt[u] = __ldcg((const float4*)&hbuf[(kc + 1) * 4096 + ((tid + 256 * u) << 2)]);
            }
            const float* wk = &w_s[(kc * 128 + ks * 16) * 32 + rg * 4];
            const float* hk = &hcur[(ks * 16) * 32 + bg * 8];
#pragma unroll
            for (int kk = 0; kk < 16; ++kk) {
                float4 w4 = *(const float4*)&wk[kk * 32];
                ulonglong2 hA = *(const ulonglong2*)&hk[kk * 32];
                ulonglong2 hB = *(const ulonglong2*)&hk[kk * 32 + 4];
                u64 w0 = dup2(w4.x), w1 = dup2(w4.y), w2 = dup2(w4.z), w3 = dup2(w4.w);
                fma2(acc[0][0], w0, hA.x); fma2(acc[0][1], w0, hA.y);
                fma2(acc[0][2], w0, hB.x); fma2(acc[0][3], w0, hB.y);
                fma2(acc[1][0], w1, hA.x); fma2(acc[1][1], w1, hA.y);
                fma2(acc[1][2], w1, hB.x); fma2(acc[1][3], w1, hB.y);
                fma2(acc[2][0], w2, hA.x); fma2(acc[2][1], w2, hA.y);
                fma2(acc[2][2], w2, hB.x); fma2(acc[2][3], w2, hB.y);
                fma2(acc[3][0], w3, hA.x); fma2(acc[3][1], w3, hA.y);
                fma2(acc[3][2], w3, hB.x); fma2(acc[3][3], w3, hB.y);
            }
        }
#pragma unroll
        for (int i = 0; i < 4; ++i) {
            *(ulonglong2*)&redu[((size_t)ks * 32 + rg * 4 + i) * 16 + bg * 4] =
                make_ulonglong2(acc[i][0], acc[i][1]);
            *(ulonglong2*)&redu[((size_t)ks * 32 + rg * 4 + i) * 16 + bg * 4 + 2] =
                make_ulonglong2(acc[i][2], acc[i][3]);
        }
        __syncthreads();
        {
            u64 o0 = redu[(size_t)ro * 16 + bq * 2];
            u64 o1 = redu[(size_t)ro * 16 + bq * 2 + 1];
#pragma unroll
            for (int s = 1; s < 8; ++s) {
                add2(o0, redu[((size_t)s * 32 + ro) * 16 + bq * 2]);
                add2(o1, redu[((size_t)s * 32 + ro) * 16 + bq * 2 + 1]);
            }
            const int b0 = bq * 4;
            float gx0 = __ldg(&g_gx[((size_t)(b0 + 0) * T_ + t) * G_ + ocol]);
            float gx1 = __ldg(&g_gx[((size_t)(b0 + 1) * T_ + t) * G_ + ocol]);
            float gx2 = __ldg(&g_gx[((size_t)(b0 + 2) * T_ + t) * G_ + ocol]);
            float gx3 = __ldg(&g_gx[((size_t)(b0 + 3) * T_ + t) * G_ + ocol]);
            add2(o0, pack2(gx0, gx1));
            add2(o1, pack2(gx2, gx3));
            float2 f0 = u2f(o0), f1 = u2f(o1);
            *(float4*)&g_s[ro * 36 + b0] = make_float4(f0.x, f0.y, f1.x, f1.y);
        }
        __syncthreads();
        {
            float fg = sigf(g_s[(0 * 8 + ju) * 36 + bu]);
            float ig = sigf(g_s[(1 * 8 + ju) * 36 + bu]);
            float og = sigf(g_s[(2 * 8 + ju) * 36 + bu]);
            float cg = tanhf(g_s[(3 * 8 + ju) * 36 + bu]);
            float cn = fg * c_reg + ig * cg;
            float hn = og * tanhf(cn);
            if (t < len_s[bu]) { c_reg = cn; h_reg = hn; }
            g_hT[(t & 1) ^ 1][(j0 + ju) * B_ + bu] = h_reg;
            outp[((size_t)bu * T_ + t) * H_ + (j0 + ju)] = h_reg;
        }
        want += NB;
        grid_bar(want);
    }
    cdst[(size_t)bu * H_ + j0 + ju] = c_reg;
    hdst[(size_t)bu * H_ + j0 + ju] = h_reg;
}

extern "C" void kernel_launch(void* const* d_in, const int* in_sizes, int n_in,
                              void* d_out, int out_size)
{
    const float* x    = (const float*)d_in[0];
    const void*  len  = d_in[1];
    const float* whh0 = (const float*)d_in[3];
    const float* b0   = (const float*)d_in[4];
    const float* whh1 = (const float*)d_in[6];
    const float* b1   = (const float*)d_in[7];
    const float* wih0 = (const float*)d_in[2];
    const float* wih1 = (const float*)d_in[5];
    float* out = (float*)d_out;

    void *bar_p, *out0_p, *ahi_p, *alo_p, *whi_p, *wlo_p;
    cudaGetSymbolAddress(&bar_p, g_bar);
    cudaGetSymbolAddress(&out0_p, g_out0);
    cudaGetSymbolAddress(&ahi_p, g_Ahi);
    cudaGetSymbolAddress(&alo_p, g_Alo);
    cudaGetSymbolAddress(&whi_p, g_Whi);
    cudaGetSymbolAddress(&wlo_p, g_Wlo);
    float* out0 = (float*)out0_p;
    __nv_bfloat16* Ahi = (__nv_bfloat16*)ahi_p;
    __nv_bfloat16* Alo = (__nv_bfloat16*)alo_p;
    __nv_bfloat16* Whi = (__nv_bfloat16*)whi_p;
    __nv_bfloat16* Wlo = (__nv_bfloat16*)wlo_p;

    cudaFuncSetAttribute(lstm_rec, cudaFuncAttributeMaxDynamicSharedMemorySize, SM_TOT);
    cudaFuncSetAttribute(tc_gemm, cudaFuncAttributeMaxDynamicSharedMemorySize, TC_SMEM);

    const size_t O1 = (size_t)B_ * T_ * H_;
    float* c0dst = out + O1;
    float* c1dst = out + O1 + (size_t)B_ * H_;
    float* h0dst = out + O1 + 2 * (size_t)B_ * H_;
    float* h1dst = out + O1 + 3 * (size_t)B_ * H_;

    const int nA4 = (B_ * T_ * H_) / 4;   // 4194304
    const int nW4 = (G_ * H_) / 4;        // 1048576
    dim3 gg(G_ / 128, (B_ * T_) / 128);   // (32, 128)

    // layer 0
    conv_split<<<nW4 / 256, 256>>>(wih0, Whi, Wlo, nW4);
    conv_split<<<nA4 / 256, 256>>>(x, Ahi, Alo, nA4);
    tc_gemm<<<gg, 256, TC_SMEM>>>(Ahi, Alo, Whi, Wlo, b0);
    cudaMemsetAsync(bar_p, 0, sizeof(unsigned), 0);
    lstm_rec<<<NB, 256, SM_TOT>>>(whh0, len, out0, c0dst, h0dst);

    // layer 1
    conv_split<<<nW4 / 256, 256>>>(wih1, Whi, Wlo, nW4);
    conv_split<<<nA4 / 256, 256>>>(out0, Ahi, Alo, nA4);
    tc_gemm<<<gg, 256, TC_SMEM>>>(Ahi, Alo, Whi, Wlo, b1);
    cudaMemsetAsync(bar_p, 0, sizeof(unsigned), 0);
    lstm_rec<<<NB, 256, SM_TOT>>>(whh1, len, out, c1dst, h1dst);
}

// round 5
// speedup vs baseline: 1.9866x; 1.0578x over previous
#include <cuda_runtime.h>
#include <cuda_bf16.h>
#include <cstddef>

#define B_ 32
#define T_ 512
#define H_ 1024
#define G_ 4096
#define NB 128

__device__ float g_gx[(size_t)B_ * T_ * G_];
__device__ float g_out0[(size_t)B_ * T_ * H_];
__device__ __nv_bfloat16 g_hb[2][2][(size_t)B_ * H_];   // [buf][hi/lo][b*1024+k]
__device__ unsigned g_bar;
__device__ __nv_bfloat16 g_Ahi[(size_t)B_ * T_ * H_];
__device__ __nv_bfloat16 g_Alo[(size_t)B_ * T_ * H_];
__device__ __nv_bfloat16 g_Whi[(size_t)G_ * H_];
__device__ __nv_bfloat16 g_Wlo[(size_t)G_ * H_];

// ---------------- hi/lo bf16 split conversion ---------------------------------
__global__ __launch_bounds__(256) void conv_split(
    const float* __restrict__ s, __nv_bfloat16* __restrict__ hi,
    __nv_bfloat16* __restrict__ lo, int n4)
{
    int i = blockIdx.x * 256 + threadIdx.x;
    if (i >= n4) return;
    float4 v = ((const float4*)s)[i];
    __nv_bfloat16 h0 = __float2bfloat16(v.x), h1 = __float2bfloat16(v.y);
    __nv_bfloat16 h2 = __float2bfloat16(v.z), h3 = __float2bfloat16(v.w);
    __nv_bfloat16 l0 = __float2bfloat16(v.x - __bfloat162float(h0));
    __nv_bfloat16 l1 = __float2bfloat16(v.y - __bfloat162float(h1));
    __nv_bfloat16 l2 = __float2bfloat16(v.z - __bfloat162float(h2));
    __nv_bfloat16 l3 = __float2bfloat16(v.w - __bfloat162float(h3));
    ((__nv_bfloat162*)hi)[i * 2]     = __nv_bfloat162(h0, h1);
    ((__nv_bfloat162*)hi)[i * 2 + 1] = __nv_bfloat162(h2, h3);
    ((__nv_bfloat162*)lo)[i * 2]     = __nv_bfloat162(l0, l1);
    ((__nv_bfloat162*)lo)[i * 2 + 1] = __nv_bfloat162(l2, l3);
}

// ---------------- mma helpers --------------------------------------------------
__device__ __forceinline__ void ldsm4(unsigned* r, unsigned a) {
    asm volatile("ldmatrix.sync.aligned.m8n8.x4.shared.b16 {%0,%1,%2,%3}, [%4];"
                 : "=r"(r[0]), "=r"(r[1]), "=r"(r[2]), "=r"(r[3]) : "r"(a));
}
__device__ __forceinline__ void mma16816(float* c, const unsigned* a,
                                         unsigned b0, unsigned b1) {
    asm volatile(
        "mma.sync.aligned.m16n8k16.row.col.f32.bf16.bf16.f32 "
        "{%0,%1,%2,%3}, {%4,%5,%6,%7}, {%8,%9}, {%0,%1,%2,%3};"
        : "+f"(c[0]), "+f"(c[1]), "+f"(c[2]), "+f"(c[3])
        : "r"(a[0]), "r"(a[1]), "r"(a[2]), "r"(a[3]), "r"(b0), "r"(b1));
}
__device__ __forceinline__ void cpa(unsigned s, const void* g) {
    asm volatile("cp.async.cg.shared.global [%0], [%1], 16;" :: "r"(s), "l"(g));
}

// ---------------- tensor-core GEMM: g_gx = A@W^T + bias (bf16x3 split) --------
#define SR 40
#define BUFB (128 * SR * 2)
#define OFF_AH 0
#define OFF_AL (2 * BUFB)
#define OFF_BH (4 * BUFB)
#define OFF_BL (6 * BUFB)
#define TC_SMEM (8 * BUFB)

__global__ __launch_bounds__(256, 1) void tc_gemm(
    const __nv_bfloat16* __restrict__ Ahi, const __nv_bfloat16* __restrict__ Alo,
    const __nv_bfloat16* __restrict__ Whi, const __nv_bfloat16* __restrict__ Wlo,
    const float* __restrict__ bias)
{
    extern __shared__ char sm[];
    const unsigned sbase = (unsigned)__cvta_generic_to_shared(sm);
    const int tid = threadIdx.x, lane = tid & 31, wid = tid >> 5;
    const int wm = wid & 3, wn = wid >> 2;
    const int m0 = blockIdx.y * 128, n0 = blockIdx.x * 128;

    int frow[2], fch[2];
    unsigned sA[2];
#pragma unroll
    for (int u = 0; u < 2; ++u) {
        int id = tid + 256 * u;
        frow[u] = id >> 2; fch[u] = (id & 3) * 8;
        sA[u] = (frow[u] * SR + fch[u]) * 2;
    }
    const int arow = wm * 32 + (lane & 7) + (lane & 8);
    const unsigned a_base = (arow * SR + (lane >> 4) * 8) * 2;
    const int brow = wn * 64 + (lane & 7) + (lane >> 4) * 8;
    const unsigned b_base = (brow * SR + ((lane >> 3) & 1) * 8) * 2;

    float c[2][8][4];
#pragma unroll
    for (int i = 0; i < 2; ++i)
#pragma unroll
        for (int j = 0; j < 8; ++j)
#pragma unroll
            for (int q = 0; q < 4; ++q) c[i][j][q] = 0.f;

#pragma unroll
    for (int u = 0; u < 2; ++u) {
        size_t ga = (size_t)(m0 + frow[u]) * H_ + fch[u];
        size_t gb = (size_t)(n0 + frow[u]) * H_ + fch[u];
        cpa(sbase + OFF_AH + sA[u], &Ahi[ga]);
        cpa(sbase + OFF_AL + sA[u], &Alo[ga]);
        cpa(sbase + OFF_BH + sA[u], &Whi[gb]);
        cpa(sbase + OFF_BL + sA[u], &Wlo[gb]);
    }
    asm volatile("cp.async.commit_group;");

    for (int s = 0; s < 32; ++s) {
        asm volatile("cp.async.wait_group 0;");
        __syncthreads();
        if (s + 1 < 32) {
            int k0 = (s + 1) * 32, bf = (s + 1) & 1;
#pragma unroll
            for (int u = 0; u < 2; ++u) {
                size_t ga = (size_t)(m0 + frow[u]) * H_ + k0 + fch[u];
                size_t gb = (size_t)(n0 + frow[u]) * H_ + k0 + fch[u];
                cpa(sbase + OFF_AH + bf * BUFB + sA[u], &Ahi[ga]);
                cpa(sbase + OFF_AL + bf * BUFB + sA[u], &Alo[ga]);
                cpa(sbase + OFF_BH + bf * BUFB + sA[u], &Whi[gb]);
                cpa(sbase + OFF_BL + bf * BUFB + sA[u], &Wlo[gb]);
            }
            asm volatile("cp.async.commit_group;");
        }
        const unsigned bo = (s & 1) * BUFB;
#pragma unroll
        for (int kk = 0; kk < 2; ++kk) {
            unsigned ah[2][4], al[2][4], bh[4][4], bl[4][4];
#pragma unroll
            for (int mi = 0; mi < 2; ++mi) {
                unsigned ad = sbase + bo + a_base + mi * (16 * SR * 2) + kk * 32;
                ldsm4(ah[mi], ad + OFF_AH);
                ldsm4(al[mi], ad + OFF_AL);
            }
#pragma unroll
            for (int j = 0; j < 4; ++j) {
                unsigned bd = sbase + bo + b_base + j * (16 * SR * 2) + kk * 32;
                ldsm4(bh[j], bd + OFF_BH);
                ldsm4(bl[j], bd + OFF_BL);
            }
#pragma unroll
            for (int mi = 0; mi < 2; ++mi)
#pragma unroll
                for (int j = 0; j < 4; ++j) {
                    mma16816(c[mi][2*j],   ah[mi], bh[j][0], bh[j][1]);
                    mma16816(c[mi][2*j+1], ah[mi], bh[j][2], bh[j][3]);
                    mma16816(c[mi][2*j],   ah[mi], bl[j][0], bl[j][1]);
                    mma16816(c[mi][2*j+1], ah[mi], bl[j][2], bl[j][3]);
                    mma16816(c[mi][2*j],   al[mi], bh[j][0], bh[j][1]);
                    mma16816(c[mi][2*j+1], al[mi], bh[j][2], bh[j][3]);
                }
        }
        __syncthreads();
    }
#pragma unroll
    for (int mi = 0; mi < 2; ++mi) {
        int gr = m0 + wm * 32 + mi * 16 + (lane >> 2);
#pragma unroll
        for (int ni = 0; ni < 8; ++ni) {
            int gc = n0 + wn * 64 + ni * 8 + (lane & 3) * 2;
            float2 bv = *(const float2*)&bias[gc];
            float* cc = c[mi][ni];
            *(float2*)&g_gx[(size_t)gr * G_ + gc] =
                make_float2(cc[0] + bv.x, cc[1] + bv.y);
            *(float2*)&g_gx[(size_t)(gr + 8) * G_ + gc] =
                make_float2(cc[2] + bv.x, cc[3] + bv.y);
        }
    }
}

// ---------------- persistent tensorized LSTM recurrence -----------------------
__device__ __forceinline__ float sigf(float x) { return 1.0f / (1.0f + __expf(-x)); }

__device__ __forceinline__ void grid_bar(unsigned want) {
    __syncthreads();
    if (threadIdx.x == 0) {
        __threadfence();
        atomicAdd(&g_bar, 1u);
        unsigned v;
        do { asm volatile("ld.acquire.gpu.u32 %0, [%1];" : "=r"(v) : "l"(&g_bar)); }
        while (v < want);
    }
    __syncthreads();
}

// SMEM byte offsets
#define WSTR 1032                              // W row stride (bf16 elems)
#define OFF_WHI 0
#define OFF_WLO (32 * WSTR * 2)                // 66048
#define OFF_HS  (2 * 32 * WSTR * 2)            // 132096
#define HSTR 136                               // h row stride (bf16 elems)
#define HS_HILO (32 * HSTR * 2)                // 8704
#define HS_BUF  (2 * HS_HILO)                  // 17408
#define OFF_RED (OFF_HS + 2 * HS_BUF)          // 166912
#define OFF_GS  (OFF_RED + 8 * 32 * 16 * 4)    // 183296
#define OFF_LEN (OFF_GS + 32 * 36 * 4)         // 187904
#define REC_SMEM (OFF_LEN + 128)               // 188032

__global__ __launch_bounds__(256, 1) void lstm_rec(
    const float* __restrict__ whh, const void* __restrict__ len_raw,
    float* __restrict__ outp, float* __restrict__ cdst, float* __restrict__ hdst)
{
    extern __shared__ char sm[];
    const unsigned sbase = (unsigned)__cvta_generic_to_shared(sm);
    float* red = (float*)(sm + OFF_RED);       // [kw0..3][nh0..1][m32][n16]
    float* g_s = (float*)(sm + OFF_GS);        // [32][36]
    int* len_s = (int*)(sm + OFF_LEN);

    const int tid = threadIdx.x, lane = tid & 31, wid = tid >> 5;
    const int j0 = blockIdx.x * 8;

    if (tid == 0) {
        const int* L = (const int*)len_raw;
        bool is64 = true;
        for (int i = 1; i < 32; i += 2) if (L[i] != 0) { is64 = false; break; }
        for (int b = 0; b < 32; ++b) len_s[b] = is64 ? L[2 * b] : L[b];
    }

    // stage + split W_hh slice: smem row r <-> global row (r>>3)*1024 + j0 + (r&7)
    {
        const int r = tid & 31;
        const int grow = (r >> 3) * 1024 + j0 + (r & 7);
        const int k0 = (tid >> 5) * 128;
        const float* src = &whh[(size_t)grow * H_ + k0];
        __nv_bfloat162* whi = (__nv_bfloat162*)(sm + OFF_WHI);
        __nv_bfloat162* wlo = (__nv_bfloat162*)(sm + OFF_WLO);
#pragma unroll
        for (int kk = 0; kk < 128; kk += 4) {
            float4 v = *(const float4*)&src[kk];
            __nv_bfloat16 h0 = __float2bfloat16(v.x), h1 = __float2bfloat16(v.y);
            __nv_bfloat16 h2 = __float2bfloat16(v.z), h3 = __float2bfloat16(v.w);
            int e = r * WSTR + k0 + kk;
            whi[e / 2]     = __nv_bfloat162(h0, h1);
            whi[e / 2 + 1] = __nv_bfloat162(h2, h3);
            wlo[e / 2]     = __nv_bfloat162(__float2bfloat16(v.x - __bfloat162float(h0)),
                                            __float2bfloat16(v.y - __bfloat162float(h1)));
            wlo[e / 2 + 1] = __nv_bfloat162(__float2bfloat16(v.z - __bfloat162float(h2)),
                                            __float2bfloat16(v.w - __bfloat162float(h3)));
        }
    }

    // warp roles: kw = K-slice (4), nh = N-half (2)
    const int kw = wid >> 1, nh = wid & 1;
    const unsigned a_off = ((lane & 7) + (lane & 8)) * (WSTR * 2) + ((lane >> 4) * 8) * 2;
    const unsigned b_off = ((nh * 16 + (lane & 7) + (lane >> 4) * 8) * HSTR
                            + ((lane >> 3) & 1) * 8) * 2;

    // h-chunk staging map: thread -> (hilo, b, 32-elem k segment)
    const int shl = tid >> 7, srem = tid & 127;
    const int sb = srem >> 2, sk = (srem & 3) * 32;
    const unsigned s_dst = OFF_HS + shl * HS_HILO + (sb * HSTR + sk) * 2;

    // reduce / gx map
    const int ro = tid >> 3, bq = tid & 7, b0g = bq * 4;
    const int rnh = b0g >> 4, rnl = b0g & 15;
    const size_t ocol = (size_t)(ro >> 3) * 1024 + j0 + (ro & 7);

    // update map
    const int ju = tid & 7, bu = tid >> 3;
    float c_reg = 0.f, h_reg = 0.f;
    ((__nv_bfloat16*)g_hb[0][0])[bu * H_ + j0 + ju] = __float2bfloat16(0.f);
    ((__nv_bfloat16*)g_hb[0][1])[bu * H_ + j0 + ju] = __float2bfloat16(0.f);

    unsigned want = NB;
    grid_bar(want);

    for (int t = 0; t < T_; ++t) {
        // prefetch gx for reduce phase
        float gxv[4];
#pragma unroll
        for (int e = 0; e < 4; ++e)
            gxv[e] = __ldg(&g_gx[((size_t)(b0g + e) * T_ + t) * G_ + ocol]);

        const __nv_bfloat16* hsrc = g_hb[t & 1][shl];
        // preload + stage chunk 0
        uint4 nxt[4];
#pragma unroll
        for (int u = 0; u < 4; ++u)
            nxt[u] = __ldcg((const uint4*)&hsrc[(size_t)sb * H_ + sk] + u);
#pragma unroll
        for (int u = 0; u < 4; ++u)
            *(uint4*)(sm + s_dst + u * 16) = nxt[u];
        __syncthreads();

        float c[2][2][4];
#pragma unroll
        for (int mi = 0; mi < 2; ++mi)
#pragma unroll
            for (int nj = 0; nj < 2; ++nj)
#pragma unroll
                for (int q = 0; q < 4; ++q) c[mi][nj][q] = 0.f;

        for (int kc = 0; kc < 8; ++kc) {
            if (kc < 7) {
#pragma unroll
                for (int u = 0; u < 4; ++u)
                    nxt[u] = __ldcg((const uint4*)&hsrc[(size_t)sb * H_ + (kc + 1) * 128 + sk] + u);
            }
            const unsigned hb_s = sbase + OFF_HS + (kc & 1) * HS_BUF;
#pragma unroll
            for (int ks = 0; ks < 2; ++ks) {
                const int kloc = kw * 32 + ks * 16;           // k within chunk
                const int kg = kc * 128 + kloc;               // k within W
                unsigned ah[2][4], al[2][4], bh[4], bl[4];
                unsigned bd = hb_s + b_off + kloc * 2;
                ldsm4(bh, bd);
                ldsm4(bl, bd + HS_HILO);
#pragma unroll
                for (int mi = 0; mi < 2; ++mi) {
                    unsigned ad = sbase + a_off + (mi * 16 * WSTR + kg) * 2;
                    ldsm4(ah[mi], ad + OFF_WHI);
                    ldsm4(al[mi], ad + OFF_WLO);
                }
#pragma unroll
                for (int mi = 0; mi < 2; ++mi)
#pragma unroll
                    for (int nj = 0; nj < 2; ++nj) {
                        mma16816(c[mi][nj], ah[mi], bh[2*nj], bh[2*nj+1]);
                        mma16816(c[mi][nj], ah[mi], bl[2*nj], bl[2*nj+1]);
                        mma16816(c[mi][nj], al[mi], bh[2*nj], bh[2*nj+1]);
                    }
            }
            if (kc < 7) {
                const unsigned nb_s = s_dst + ((kc + 1) & 1) * HS_BUF;
#pragma unroll
                for (int u = 0; u < 4; ++u)
                    *(uint4*)(sm + nb_s + u * 16) = nxt[u];
                __syncthreads();
            }
        }

        // store partials: red[kw][nh][m][16]
#pragma unroll
        for (int mi = 0; mi < 2; ++mi)
#pragma unroll
            for (int nj = 0; nj < 2; ++nj) {
                int m = mi * 16 + (lane >> 2);
                int nl = nj * 8 + (lane & 3) * 2;
                float* rb = &red[((kw * 2 + nh) * 32) * 16];
                *(float2*)&rb[m * 16 + nl]       = make_float2(c[mi][nj][0], c[mi][nj][1]);
                *(float2*)&rb[(m + 8) * 16 + nl] = make_float2(c[mi][nj][2], c[mi][nj][3]);
            }
        __syncthreads();

        // reduce over kw, add gx, write gates
        {
            float4 s0 = *(float4*)&red[((0 * 2 + rnh) * 32 + ro) * 16 + rnl];
#pragma unroll
            for (int s = 1; s < 4; ++s) {
                float4 p = *(float4*)&red[((s * 2 + rnh) * 32 + ro) * 16 + rnl];
                s0.x += p.x; s0.y += p.y; s0.z += p.z; s0.w += p.w;
            }
            *(float4*)&g_s[ro * 36 + b0g] = make_float4(
                s0.x + gxv[0], s0.y + gxv[1], s0.z + gxv[2], s0.w + gxv[3]);
        }
        __syncthreads();

        // pointwise update (fp32 state)
        {
            float fg = sigf(g_s[(0 * 8 + ju) * 36 + bu]);
            float ig = sigf(g_s[(1 * 8 + ju) * 36 + bu]);
            float og = sigf(g_s[(2 * 8 + ju) * 36 + bu]);
            float cg = tanhf(g_s[(3 * 8 + ju) * 36 + bu]);
            float cn = fg * c_reg + ig * cg;
            float hn = og * tanhf(cn);
            if (t < len_s[bu]) { c_reg = cn; h_reg = hn; }
            __nv_bfloat16 hh = __float2bfloat16(h_reg);
            __nv_bfloat16 hl = __float2bfloat16(h_reg - __bfloat162float(hh));
            int nbuf = (t & 1) ^ 1;
            g_hb[nbuf][0][bu * H_ + j0 + ju] = hh;
            g_hb[nbuf][1][bu * H_ + j0 + ju] = hl;
            outp[((size_t)bu * T_ + t) * H_ + (j0 + ju)] = h_reg;
        }

        want += NB;
        grid_bar(want);
    }
    cdst[(size_t)bu * H_ + j0 + ju] = c_reg;
    hdst[(size_t)bu * H_ + j0 + ju] = h_reg;
}

extern "C" void kernel_launch(void* const* d_in, const int* in_sizes, int n_in,
                              void* d_out, int out_size)
{
    const float* x    = (const float*)d_in[0];
    const void*  len  = d_in[1];
    const float* wih0 = (const float*)d_in[2];
    const float* whh0 = (const float*)d_in[3];
    const float* b0   = (const float*)d_in[4];
    const float* wih1 = (const float*)d_in[5];
    const float* whh1 = (const float*)d_in[6];
    const float* b1   = (const float*)d_in[7];
    float* out = (float*)d_out;

    void *bar_p, *out0_p, *ahi_p, *alo_p, *whi_p, *wlo_p;
    cudaGetSymbolAddress(&bar_p, g_bar);
    cudaGetSymbolAddress(&out0_p, g_out0);
    cudaGetSymbolAddress(&ahi_p, g_Ahi);
    cudaGetSymbolAddress(&alo_p, g_Alo);
    cudaGetSymbolAddress(&whi_p, g_Whi);
    cudaGetSymbolAddress(&wlo_p, g_Wlo);
    float* out0 = (float*)out0_p;
    __nv_bfloat16* Ahi = (__nv_bfloat16*)ahi_p;
    __nv_bfloat16* Alo = (__nv_bfloat16*)alo_p;
    __nv_bfloat16* Whi = (__nv_bfloat16*)whi_p;
    __nv_bfloat16* Wlo = (__nv_bfloat16*)wlo_p;

    cudaFuncSetAttribute(lstm_rec, cudaFuncAttributeMaxDynamicSharedMemorySize, REC_SMEM);
    cudaFuncSetAttribute(tc_gemm, cudaFuncAttributeMaxDynamicSharedMemorySize, TC_SMEM);

    const size_t O1 = (size_t)B_ * T_ * H_;
    float* c0dst = out + O1;
    float* c1dst = out + O1 + (size_t)B_ * H_;
    float* h0dst = out + O1 + 2 * (size_t)B_ * H_;
    float* h1dst = out + O1 + 3 * (size_t)B_ * H_;

    const int nA4 = (B_ * T_ * H_) / 4;
    const int nW4 = (G_ * H_) / 4;
    dim3 gg(G_ / 128, (B_ * T_) / 128);

    conv_split<<<nW4 / 256, 256>>>(wih0, Whi, Wlo, nW4);
    conv_split<<<nA4 / 256, 256>>>(x, Ahi, Alo, nA4);
    tc_gemm<<<gg, 256, TC_SMEM>>>(Ahi, Alo, Whi, Wlo, b0);
    cudaMemsetAsync(bar_p, 0, sizeof(unsigned), 0);
    lstm_rec<<<NB, 256, REC_SMEM>>>(whh0, len, out0, c0dst, h0dst);

    conv_split<<<nW4 / 256, 256>>>(wih1, Whi, Wlo, nW4);
    conv_split<<<nA4 / 256, 256>>>(out0, Ahi, Alo, nA4);
    tc_gemm<<<gg, 256, TC_SMEM>>>(Ahi, Alo, Whi, Wlo, b1);
    cudaMemsetAsync(bar_p, 0, sizeof(unsigned), 0);
    lstm_rec<<<NB, 256, REC_SMEM>>>(whh1, len, out, c1dst, h1dst);
}